// round 2
// baseline (speedup 1.0000x reference)
#include <cuda_runtime.h>
#include <math.h>

// Problem constants (fixed dataset)
#define NN      50000
#define EE      1600000
#define FIN     256
#define H       4
#define D       32
#define HD      128     // H*D
#define C       16      // num classes

// ---------------- scratch (device globals; no allocation allowed) ----------
__device__ __align__(16) float g_feat1[NN * HD];
__device__ __align__(16) float g_el1[NN * H];
__device__ __align__(16) float g_er1[NN * H];
__device__ __align__(16) float g_w1[EE * H];
__device__ __align__(16) float g_denom1[NN * H];
__device__ __align__(16) float g_acc1[NN * HD];
__device__ __align__(16) float g_h[NN * HD];
__device__ __align__(16) float g_feat2[NN * C];
__device__ __align__(16) float g_el2[NN];
__device__ __align__(16) float g_er2[NN];
__device__ __align__(16) float g_w2[EE];
__device__ __align__(16) float g_denom2[NN];
__device__ __align__(16) float g_acc2[NN * C];

__device__ __forceinline__ void red4(float* p, float a, float b, float c, float d) {
    asm volatile("red.global.add.v4.f32 [%0], {%1,%2,%3,%4};"
                 :: "l"(p), "f"(a), "f"(b), "f"(c), "f"(d) : "memory");
}

__device__ __forceinline__ float lrelu(float v) { return v > 0.f ? v : 0.2f * v; }
__device__ __forceinline__ float elu1(float v)  { return v > 0.f ? v : (expf(v) - 1.f); }

// ---------------- K0: zero accumulators --------------------------------
// acc1: 1,600,000 float4 | denom1: 50,000 | acc2: 200,000 | denom2: 12,500
// total float4 = 1,862,500
__global__ void k_zero() {
    int i = blockIdx.x * blockDim.x + threadIdx.x;
    float4 z = make_float4(0.f, 0.f, 0.f, 0.f);
    if (i < 1600000) {
        ((float4*)g_acc1)[i] = z;
    } else if (i < 1650000) {
        ((float4*)g_denom1)[i - 1600000] = z;
    } else if (i < 1850000) {
        ((float4*)g_acc2)[i - 1650000] = z;
    } else if (i < 1862500) {
        ((float4*)g_denom2)[i - 1850000] = z;
    }
}

// ---------------- K1: feat1 = x @ W1   [N,256]x[256,128] ----------------
__global__ __launch_bounds__(256) void k_gemm1(const float* __restrict__ x,
                                               const float* __restrict__ W1,
                                               int n) {
    __shared__ float xs[64][32];
    __shared__ float ws[32][128];
    int t = threadIdx.x;
    int row0 = blockIdx.x * 64;
    int c0 = (t & 31) * 4;
    int r0 = (t >> 5) * 8;
    float acc[8][4];
#pragma unroll
    for (int i = 0; i < 8; i++) { acc[i][0]=0.f; acc[i][1]=0.f; acc[i][2]=0.f; acc[i][3]=0.f; }

    for (int k0 = 0; k0 < FIN; k0 += 32) {
        {
            int rl = t >> 3;            // 0..31
            int kc = (t & 7) * 4;       // 0..28
#pragma unroll
            for (int i = 0; i < 2; i++) {
                int r = rl + i * 32;
                int gr = row0 + r;
                float4 v = make_float4(0.f, 0.f, 0.f, 0.f);
                if (gr < n) v = *(const float4*)&x[(long)gr * FIN + k0 + kc];
                *(float4*)&xs[r][kc] = v;
            }
        }
        {
            int kl = t >> 5;            // 0..7
            int col = (t & 31) * 4;
#pragma unroll
            for (int i = 0; i < 4; i++) {
                int kr = kl + i * 8;
                *(float4*)&ws[kr][col] = *(const float4*)&W1[(k0 + kr) * HD + col];
            }
        }
        __syncthreads();
#pragma unroll
        for (int k = 0; k < 32; k++) {
            float4 w4 = *(float4*)&ws[k][c0];
#pragma unroll
            for (int i = 0; i < 8; i++) {
                float xv = xs[r0 + i][k];
                acc[i][0] += xv * w4.x;
                acc[i][1] += xv * w4.y;
                acc[i][2] += xv * w4.z;
                acc[i][3] += xv * w4.w;
            }
        }
        __syncthreads();
    }
#pragma unroll
    for (int i = 0; i < 8; i++) {
        int gr = row0 + r0 + i;
        if (gr < n)
            *(float4*)&g_feat1[(long)gr * HD + c0] =
                make_float4(acc[i][0], acc[i][1], acc[i][2], acc[i][3]);
    }
}

// ---------------- K2: el/er per (node, head) ----------------------------
__global__ __launch_bounds__(256) void k_elr(const float* __restrict__ al1,
                                             const float* __restrict__ ar1, int n) {
    int i = blockIdx.x * blockDim.x + threadIdx.x;
    if (i >= n * H) return;
    int node = i >> 2, h = i & 3;
    const float* f = &g_feat1[(long)node * HD + h * D];
    float el = 0.f, er = 0.f;
#pragma unroll
    for (int j = 0; j < D; j++) {
        float v = f[j];
        el += v * al1[h * D + j];
        er += v * ar1[h * D + j];
    }
    g_el1[i] = el;
    g_er1[i] = er;
}

// ---------------- K3: per-edge weights + denom (layer 1) ----------------
__global__ __launch_bounds__(256) void k_edge1(const int* __restrict__ src,
                                               const int* __restrict__ dst, int e_cnt) {
    int e = blockIdx.x * blockDim.x + threadIdx.x;
    if (e >= e_cnt) return;
    int s = src[e], d = dst[e];
    float4 el = *(const float4*)&g_el1[s * 4];
    float4 er = *(const float4*)&g_er1[d * 4];
    float w0 = expf(lrelu(el.x + er.x));
    float w1 = expf(lrelu(el.y + er.y));
    float w2 = expf(lrelu(el.z + er.z));
    float w3 = expf(lrelu(el.w + er.w));
    *(float4*)&g_w1[(long)e * 4] = make_float4(w0, w1, w2, w3);
    red4(&g_denom1[d * 4], w0, w1, w2, w3);
}

// ---------------- K4: edge aggregation (layer 1), one warp per edge -----
__global__ __launch_bounds__(256) void k_agg1(const int* __restrict__ src,
                                              const int* __restrict__ dst, int e_cnt) {
    unsigned gid = blockIdx.x * blockDim.x + threadIdx.x;
    unsigned e = gid >> 5;
    if (e >= (unsigned)e_cnt) return;
    int lane = gid & 31;
    int s = __ldg(&src[e]);
    int d = __ldg(&dst[e]);
    float w = __ldg(&g_w1[(long)e * 4 + (lane >> 3)]);
    float4 f = *(const float4*)&g_feat1[(long)s * HD + lane * 4];
    red4(&g_acc1[(long)d * HD + lane * 4], f.x * w, f.y * w, f.z * w, f.w * w);
}

// ---------------- K5: h = elu(acc/denom + b1) ---------------------------
__global__ __launch_bounds__(256) void k_act1(const float* __restrict__ b1, int n) {
    int i = blockIdx.x * blockDim.x + threadIdx.x;   // one per float4 of [N,128]
    if (i >= n * 32) return;
    int node = i >> 5, q = i & 31;
    int head = q >> 3;
    float denom = fmaxf(g_denom1[node * 4 + head], 1e-9f);
    float inv = 1.f / denom;
    float4 a = *(const float4*)&g_acc1[(long)node * HD + q * 4];
    float4 b = *(const float4*)&b1[q * 4];
    float4 o;
    o.x = elu1(a.x * inv + b.x);
    o.y = elu1(a.y * inv + b.y);
    o.z = elu1(a.z * inv + b.z);
    o.w = elu1(a.w * inv + b.w);
    *(float4*)&g_h[(long)node * HD + q * 4] = o;
}

// ---------------- K6: feat2 = h @ W2 [N,128]x[128,16], + el2/er2 --------
__global__ __launch_bounds__(256) void k_gemm2(const float* __restrict__ W2,
                                               const float* __restrict__ al2,
                                               const float* __restrict__ ar2, int n) {
    __shared__ float w2s[HD * C];   // 8KB
    __shared__ float al2s[C], ar2s[C];
    int t = threadIdx.x;
    for (int j = t; j < HD * C; j += 256) w2s[j] = W2[j];
    if (t < C) { al2s[t] = al2[t]; ar2s[t] = ar2[t]; }
    __syncthreads();
    int node = blockIdx.x * 256 + t;
    if (node >= n) return;
    float acc[C];
#pragma unroll
    for (int c = 0; c < C; c++) acc[c] = 0.f;
    const float* hr = &g_h[(long)node * HD];
#pragma unroll 4
    for (int kk = 0; kk < 32; kk++) {
        float4 f = *(const float4*)&hr[kk * 4];
        const float* wrow = &w2s[(kk * 4) * C];
#pragma unroll
        for (int c = 0; c < C; c++) {
            acc[c] += f.x * wrow[c] + f.y * wrow[C + c] + f.z * wrow[2 * C + c] + f.w * wrow[3 * C + c];
        }
    }
    float el = 0.f, er = 0.f;
#pragma unroll
    for (int c = 0; c < C; c++) { el += acc[c] * al2s[c]; er += acc[c] * ar2s[c]; }
    float* out = &g_feat2[(long)node * C];
#pragma unroll
    for (int c4 = 0; c4 < 4; c4++)
        *(float4*)&out[c4 * 4] = make_float4(acc[c4 * 4], acc[c4 * 4 + 1], acc[c4 * 4 + 2], acc[c4 * 4 + 3]);
    g_el2[node] = el;
    g_er2[node] = er;
}

// ---------------- K7: per-edge weights + denom (layer 2) ----------------
__global__ __launch_bounds__(256) void k_edge2(const int* __restrict__ src,
                                               const int* __restrict__ dst, int e_cnt) {
    int e = blockIdx.x * blockDim.x + threadIdx.x;
    if (e >= e_cnt) return;
    int s = src[e], d = dst[e];
    float w = expf(lrelu(g_el2[s] + g_er2[d]));
    g_w2[e] = w;
    atomicAdd(&g_denom2[d], w);
}

// ---------------- K8: edge aggregation (layer 2), 4 lanes per edge ------
__global__ __launch_bounds__(256) void k_agg2(const int* __restrict__ src,
                                              const int* __restrict__ dst, int e_cnt) {
    unsigned gid = blockIdx.x * blockDim.x + threadIdx.x;
    unsigned e = gid >> 2;
    if (e >= (unsigned)e_cnt) return;
    int sub = gid & 3;
    int s = __ldg(&src[e]);
    int d = __ldg(&dst[e]);
    float w = __ldg(&g_w2[e]);
    float4 f = *(const float4*)&g_feat2[(long)s * C + sub * 4];
    red4(&g_acc2[(long)d * C + sub * 4], f.x * w, f.y * w, f.z * w, f.w * w);
}

// ---------------- K9: final output --------------------------------------
__global__ __launch_bounds__(256) void k_final(const float* __restrict__ b2,
                                               float* __restrict__ out, int n) {
    int i = blockIdx.x * blockDim.x + threadIdx.x;   // one per float4 of [N,16]
    if (i >= n * 4) return;
    int node = i >> 2, sub = i & 3;
    float inv = 1.f / fmaxf(g_denom2[node], 1e-9f);
    float4 a = *(const float4*)&g_acc2[(long)node * C + sub * 4];
    float4 b = *(const float4*)&b2[sub * 4];
    float4 o = make_float4(a.x * inv + b.x, a.y * inv + b.y, a.z * inv + b.z, a.w * inv + b.w);
    *(float4*)&out[(long)node * C + sub * 4] = o;
}

extern "C" void kernel_launch(void* const* d_in, const int* in_sizes, int n_in,
                              void* d_out, int out_size) {
    const float* x   = (const float*)d_in[0];
    const int*   src = (const int*)d_in[1];
    const int*   dst = (const int*)d_in[2];
    const float* W1  = (const float*)d_in[3];
    const float* b1  = (const float*)d_in[4];
    const float* al1 = (const float*)d_in[5];
    const float* ar1 = (const float*)d_in[6];
    const float* W2  = (const float*)d_in[7];
    const float* b2  = (const float*)d_in[8];
    const float* al2 = (const float*)d_in[9];
    const float* ar2 = (const float*)d_in[10];
    float* out = (float*)d_out;

    int n = in_sizes[0] / FIN;   // 50000
    int e = in_sizes[1];         // 1600000

    k_zero<<<(1862500 + 255) / 256, 256>>>();
    k_gemm1<<<(n + 63) / 64, 256>>>(x, W1, n);
    k_elr<<<(n * H + 255) / 256, 256>>>(al1, ar1, n);
    k_edge1<<<(e + 255) / 256, 256>>>(src, dst, e);
    {
        unsigned long long th = (unsigned long long)e * 32ull;
        k_agg1<<<(unsigned)((th + 255) / 256), 256>>>(src, dst, e);
    }
    k_act1<<<(n * 32 + 255) / 256, 256>>>(b1, n);
    k_gemm2<<<(n + 255) / 256, 256>>>(W2, al2, ar2, n);
    k_edge2<<<(e + 255) / 256, 256>>>(src, dst, e);
    k_agg2<<<((unsigned)e * 4 + 255) / 256, 256>>>(src, dst, e);
    k_final<<<(n * 4 + 255) / 256, 256>>>(b2, out, n);
}

// round 4
// speedup vs baseline: 1.5462x; 1.5462x over previous
#include <cuda_runtime.h>
#include <math.h>

#define NN      50000
#define EE      1600000
#define FIN     256
#define H       4
#define D       32
#define HD      128
#define C       16
#define NBLK    196     // ceil(NN/256)

// ---------------- scratch ------------------------------------------------
__device__ __align__(16) float g_feat1[NN * HD];
__device__ __align__(16) float g_el1[NN * H];
__device__ __align__(16) float g_er1[NN * H];
__device__ __align__(16) float g_h[NN * HD];
__device__ __align__(16) float g_feat2[NN * C];
__device__ __align__(16) float g_el2[NN];
__device__ __align__(16) float g_er2[NN];
// CSR build
__device__ int g_cnt[NN];
__device__ int g_off[NN + 1];
__device__ int g_cur[NN];
__device__ int g_ebuf[EE];     // src node id, sorted by dst
__device__ int g_bsum[NBLK];
__device__ int g_bpre[NBLK + 1];

__device__ __forceinline__ float lrelu(float v) { return v > 0.f ? v : 0.2f * v; }
__device__ __forceinline__ float elu1(float v)  { return v > 0.f ? v : (__expf(v) - 1.f); }

// ---------------- CSR build ---------------------------------------------
__global__ void k_zero_cnt() {
    int i = blockIdx.x * blockDim.x + threadIdx.x;
    if (i < NN) g_cnt[i] = 0;
}

__global__ void k_hist(const int* __restrict__ dst, int e_cnt) {
    int e = blockIdx.x * blockDim.x + threadIdx.x;
    if (e < e_cnt) atomicAdd(&g_cnt[dst[e]], 1);
}

// block-level exclusive scan of g_cnt -> g_off (local), block sums -> g_bsum
__global__ void k_scan1() {
    __shared__ int sh[256];
    int t = threadIdx.x;
    int i = blockIdx.x * 256 + t;
    int v = (i < NN) ? g_cnt[i] : 0;
    sh[t] = v;
    __syncthreads();
#pragma unroll
    for (int ofs = 1; ofs < 256; ofs <<= 1) {
        int x = (t >= ofs) ? sh[t - ofs] : 0;
        __syncthreads();
        sh[t] += x;
        __syncthreads();
    }
    if (i < NN) g_off[i] = sh[t] - v;           // exclusive
    if (t == 255) g_bsum[blockIdx.x] = sh[255];
}

__global__ void k_scan2() {
    __shared__ int sh[256];
    int t = threadIdx.x;
    int v = (t < NBLK) ? g_bsum[t] : 0;
    sh[t] = v;
    __syncthreads();
#pragma unroll
    for (int ofs = 1; ofs < 256; ofs <<= 1) {
        int x = (t >= ofs) ? sh[t - ofs] : 0;
        __syncthreads();
        sh[t] += x;
        __syncthreads();
    }
    if (t < NBLK) g_bpre[t] = sh[t] - v;        // exclusive
}

__global__ void k_scan3(int e_cnt) {
    int i = blockIdx.x * blockDim.x + threadIdx.x;
    if (i < NN) {
        int o = g_off[i] + g_bpre[i >> 8];
        g_off[i] = o;
        g_cur[i] = o;
    }
    if (i == 0) g_off[NN] = e_cnt;
}

__global__ void k_scatter(const int* __restrict__ src, const int* __restrict__ dst, int e_cnt) {
    int e = blockIdx.x * blockDim.x + threadIdx.x;
    if (e >= e_cnt) return;
    int pos = atomicAdd(&g_cur[dst[e]], 1);
    g_ebuf[pos] = src[e];
}

// ---------------- K1: feat1 = x @ W1, fused el/er epilogue --------------
__global__ __launch_bounds__(256) void k_gemm1(const float* __restrict__ x,
                                               const float* __restrict__ W1,
                                               const float* __restrict__ al1,
                                               const float* __restrict__ ar1,
                                               int n) {
    __shared__ float xs[64][32];
    __shared__ float ws[32][128];
    int t = threadIdx.x;
    int lane = t & 31;
    int row0 = blockIdx.x * 64;
    int c0 = lane * 4;
    int r0 = (t >> 5) * 8;
    float acc[8][4];
#pragma unroll
    for (int i = 0; i < 8; i++) { acc[i][0]=0.f; acc[i][1]=0.f; acc[i][2]=0.f; acc[i][3]=0.f; }

    for (int k0 = 0; k0 < FIN; k0 += 32) {
        {
            int rl = t >> 3;
            int kc = (t & 7) * 4;
#pragma unroll
            for (int i = 0; i < 2; i++) {
                int r = rl + i * 32;
                int gr = row0 + r;
                float4 v = make_float4(0.f, 0.f, 0.f, 0.f);
                if (gr < n) v = *(const float4*)&x[(long)gr * FIN + k0 + kc];
                *(float4*)&xs[r][kc] = v;
            }
        }
        {
            int kl = t >> 5;
#pragma unroll
            for (int i = 0; i < 4; i++) {
                int kr = kl + i * 8;
                *(float4*)&ws[kr][c0] = *(const float4*)&W1[(k0 + kr) * HD + c0];
            }
        }
        __syncthreads();
#pragma unroll
        for (int k = 0; k < 32; k++) {
            float4 w4 = *(float4*)&ws[k][c0];
#pragma unroll
            for (int i = 0; i < 8; i++) {
                float xv = xs[r0 + i][k];
                acc[i][0] += xv * w4.x;
                acc[i][1] += xv * w4.y;
                acc[i][2] += xv * w4.z;
                acc[i][3] += xv * w4.w;
            }
        }
        __syncthreads();
    }

    float4 al4 = *(const float4*)&al1[c0];   // al1 flat [128]
    float4 ar4 = *(const float4*)&ar1[c0];
    int head = lane >> 3;
#pragma unroll
    for (int i = 0; i < 8; i++) {
        int gr = row0 + r0 + i;
        float elp = acc[i][0]*al4.x + acc[i][1]*al4.y + acc[i][2]*al4.z + acc[i][3]*al4.w;
        float erp = acc[i][0]*ar4.x + acc[i][1]*ar4.y + acc[i][2]*ar4.z + acc[i][3]*ar4.w;
#pragma unroll
        for (int m = 1; m < 8; m <<= 1) {
            elp += __shfl_xor_sync(0xffffffffu, elp, m);
            erp += __shfl_xor_sync(0xffffffffu, erp, m);
        }
        if (gr < n) {
            *(float4*)&g_feat1[(long)gr * HD + c0] =
                make_float4(acc[i][0], acc[i][1], acc[i][2], acc[i][3]);
            if ((lane & 7) == 0) {
                g_el1[gr * 4 + head] = elp;
                g_er1[gr * 4 + head] = erp;
            }
        }
    }
}

// ---------------- K2: fused layer-1 attention + aggregation + act -------
// one warp per dst node; lane owns 4 consecutive feats (one head per 8 lanes)
__global__ __launch_bounds__(256) void k_layer1(const float* __restrict__ b1, int n) {
    int wid = (blockIdx.x * blockDim.x + threadIdx.x) >> 5;
    if (wid >= n) return;
    int lane = threadIdx.x & 31;
    int head = lane >> 3;
    int d = wid;
    int off0 = g_off[d], off1 = g_off[d + 1];
    float er = g_er1[d * 4 + head];
    float ax = 0.f, ay = 0.f, az = 0.f, aw = 0.f, wsum = 0.f;

    int j = off0;
    int s = (j < off1) ? __ldg(&g_ebuf[j]) : 0;
    while (j < off1) {
        int s_next = (j + 1 < off1) ? __ldg(&g_ebuf[j + 1]) : 0;
        float el = __ldg(&g_el1[s * 4 + head]);
        float4 f = *(const float4*)&g_feat1[(long)s * HD + lane * 4];
        float w = __expf(lrelu(el + er));
        ax += f.x * w; ay += f.y * w; az += f.z * w; aw += f.w * w;
        wsum += w;
        s = s_next;
        j++;
    }
    float inv = 1.f / fmaxf(wsum, 1e-9f);
    float4 b = *(const float4*)&b1[lane * 4];
    float4 o;
    o.x = elu1(ax * inv + b.x);
    o.y = elu1(ay * inv + b.y);
    o.z = elu1(az * inv + b.z);
    o.w = elu1(aw * inv + b.w);
    *(float4*)&g_h[(long)d * HD + lane * 4] = o;
}

// ---------------- K3: feat2 = h @ W2 [N,128]x[128,16] + el2/er2 ---------
__global__ __launch_bounds__(256) void k_gemm2(const float* __restrict__ W2,
                                               const float* __restrict__ al2,
                                               const float* __restrict__ ar2, int n) {
    __shared__ float w2s[HD * C];
    __shared__ float al2s[C], ar2s[C];
    int t = threadIdx.x;
    for (int j = t; j < HD * C; j += 256) w2s[j] = W2[j];
    if (t < C) { al2s[t] = al2[t]; ar2s[t] = ar2[t]; }
    __syncthreads();
    int node = blockIdx.x * 256 + t;
    if (node >= n) return;
    float acc[C];
#pragma unroll
    for (int c = 0; c < C; c++) acc[c] = 0.f;
    const float* hr = &g_h[(long)node * HD];
#pragma unroll 4
    for (int kk = 0; kk < 32; kk++) {
        float4 f = *(const float4*)&hr[kk * 4];
        const float* wrow = &w2s[(kk * 4) * C];
#pragma unroll
        for (int c = 0; c < C; c++) {
            acc[c] += f.x * wrow[c] + f.y * wrow[C + c] + f.z * wrow[2 * C + c] + f.w * wrow[3 * C + c];
        }
    }
    float el = 0.f, er = 0.f;
#pragma unroll
    for (int c = 0; c < C; c++) { el += acc[c] * al2s[c]; er += acc[c] * ar2s[c]; }
    float* out = &g_feat2[(long)node * C];
#pragma unroll
    for (int c4 = 0; c4 < 4; c4++)
        *(float4*)&out[c4 * 4] = make_float4(acc[c4*4], acc[c4*4+1], acc[c4*4+2], acc[c4*4+3]);
    g_el2[node] = el;
    g_er2[node] = er;
}

// ---------------- K4: fused layer-2 attention + aggregation + output ----
// 16 threads per dst node (one per class); 16 groups per 256-block
__global__ __launch_bounds__(256) void k_layer2(const float* __restrict__ b2,
                                                float* __restrict__ out, int n) {
    int t = threadIdx.x;
    int d = blockIdx.x * 16 + (t >> 4);
    if (d >= n) return;
    int c = t & 15;
    int off0 = g_off[d], off1 = g_off[d + 1];
    float er = g_er2[d];
    float acc = 0.f, wsum = 0.f;

    int j = off0;
    int s = (j < off1) ? __ldg(&g_ebuf[j]) : 0;
    while (j < off1) {
        int s_next = (j + 1 < off1) ? __ldg(&g_ebuf[j + 1]) : 0;
        float el = __ldg(&g_el2[s]);
        float f = __ldg(&g_feat2[(long)s * C + c]);
        float w = __expf(lrelu(el + er));
        acc += f * w;
        wsum += w;
        s = s_next;
        j++;
    }
    out[(long)d * C + c] = acc / fmaxf(wsum, 1e-9f) + __ldg(&b2[c]);
}

extern "C" void kernel_launch(void* const* d_in, const int* in_sizes, int n_in,
                              void* d_out, int out_size) {
    const float* x   = (const float*)d_in[0];
    const int*   src = (const int*)d_in[1];
    const int*   dst = (const int*)d_in[2];
    const float* W1  = (const float*)d_in[3];
    const float* b1  = (const float*)d_in[4];
    const float* al1 = (const float*)d_in[5];
    const float* ar1 = (const float*)d_in[6];
    const float* W2  = (const float*)d_in[7];
    const float* b2  = (const float*)d_in[8];
    const float* al2 = (const float*)d_in[9];
    const float* ar2 = (const float*)d_in[10];
    float* out = (float*)d_out;

    int n = in_sizes[0] / FIN;   // 50000
    int e = in_sizes[1];         // 1600000
    int eb = (e + 255) / 256;

    // CSR build (independent of gemm1)
    k_zero_cnt<<<NBLK, 256>>>();
    k_gemm1<<<(n + 63) / 64, 256>>>(x, W1, al1, ar1, n);
    k_hist<<<eb, 256>>>(dst, e);
    k_scan1<<<NBLK, 256>>>();
    k_scan2<<<1, 256>>>();
    k_scan3<<<NBLK, 256>>>(e);
    k_scatter<<<eb, 256>>>(src, dst, e);

    k_layer1<<<(n * 32 + 255) / 256, 256>>>(b1, n);
    k_gemm2<<<(n + 255) / 256, 256>>>(W2, al2, ar2, n);
    k_layer2<<<(n * 16 + 255) / 256, 256>>>(b2, out, n);
}